// round 4
// baseline (speedup 1.0000x reference)
#include <cuda_runtime.h>
#include <cstdint>

#define BATCH   32768
#define D_IN    160
#define D_H1    512
#define D_H2    1024
#define D_OUT   3072

// ---------------- scratch (static device arrays; allocation-free) -----------
// All GEMM operands stored K-permuted: within each 16-float K block, element k
// lives at position p = (k%4)*4 + k/4  (so p = 4*tg+j holds k = 4*j+tg).
__device__ float g_h1[BATCH * D_H1];    //  64 MB
__device__ float g_h2[BATCH * D_H2];    // 128 MB
__device__ float g_w2t[D_H2 * D_H1];    //   2 MB  W2^T [1024,512]
__device__ float g_w3t[D_OUT * D_H2];   //  12 MB  W3^T [3072,1024]

// ---------------- helpers ---------------------------------------------------
__device__ __forceinline__ uint32_t smem_u32(const void* p) {
    uint32_t a;
    asm("{ .reg .u64 t; cvta.to.shared.u64 t, %1; cvt.u32.u64 %0, t; }" : "=r"(a) : "l"(p));
    return a;
}
__device__ __forceinline__ float tf32_round(float v) {
    uint32_t o;
    asm("cvt.rna.tf32.f32 %0, %1;" : "=r"(o) : "f"(v));
    return __uint_as_float(o);
}
__device__ __forceinline__ int kperm(int j) { return (j & 3) * 4 + (j >> 2); }  // j in [0,16)

__device__ __forceinline__ void cp16(uint32_t dst, const void* src) {
    asm volatile("cp.async.cg.shared.global [%0], [%1], 16;" :: "r"(dst), "l"(src));
}
#define CP_COMMIT()  asm volatile("cp.async.commit_group;" ::: "memory")
#define CP_WAIT(n)   asm volatile("cp.async.wait_group %0;" :: "n"(n) : "memory")

__device__ __forceinline__ void mma_tf32(float* c,
                                         uint32_t a0, uint32_t a1, uint32_t a2, uint32_t a3,
                                         uint32_t b0, uint32_t b1) {
    asm volatile(
        "mma.sync.aligned.m16n8k8.row.col.f32.tf32.tf32.f32 "
        "{%0,%1,%2,%3}, {%4,%5,%6,%7}, {%8,%9}, {%0,%1,%2,%3};"
        : "+f"(c[0]), "+f"(c[1]), "+f"(c[2]), "+f"(c[3])
        : "r"(a0), "r"(a1), "r"(a2), "r"(a3), "r"(b0), "r"(b1));
}

// ---------------- GEMM config ----------------------------------------------
#define BM 128
#define BN 128
#define BK 16
#define STAGES 8
#define STAGE_BYTES (2 * BM * BK * 4)              // 16384 (A 8K + B 8K)
#define SMEM_BIAS   0
#define SMEM_TILES  1024
#define SMEM_DYN    (SMEM_TILES + STAGES * STAGE_BYTES)   // 132096
#define GROUP_M 16

// ---------------------------------------------------------------------------
// Pipelined tf32 mma.sync GEMM:  C[M,N] = act(A[M,K] @ Bt[N,K]^T + bias)
// A [M,K], Bt [N,K], both row-major, tf32-rounded, K-permuted per 16-block.
// 512 threads, 16 warps (4x4), warp tile 32x32, 8-stage cp.async pipeline.
// ACT: 0 = relu + tf32 round + K-permuted store (feeds next GEMM)
//      1 = sigmoid, plain row-major float2 stores
// ---------------------------------------------------------------------------
template <int ACT>
__global__ __launch_bounds__(512)
void gemm_mma(const float* __restrict__ A, const float* __restrict__ Bt,
              const float* __restrict__ bias, float* __restrict__ C,
              int M, int N, int K)
{
    extern __shared__ char smem[];
    float* bias_s = (float*)(smem + SMEM_BIAS);
    const uint32_t tiles_u32 = smem_u32(smem + SMEM_TILES);

    const int tid  = threadIdx.x;
    const int wid  = tid >> 5, lane = tid & 31;
    const int g    = lane >> 2, tg = lane & 3;
    const int wm   = wid & 3, wn = wid >> 2;          // 4 x 4 warp grid

    // grouped rasterization
    const int num_n = N / BN;
    const int tpg   = GROUP_M * num_n;
    const int grp   = blockIdx.x / tpg;
    const int rem   = blockIdx.x % tpg;
    const int m0 = (grp * GROUP_M + rem % GROUP_M) * BM;
    const int n0 = (rem / GROUP_M) * BN;

    if (tid < BN) bias_s[tid] = bias[n0 + tid];

    const int KT = K / BK;

    // stage loader: 1 A chunk + 1 B chunk (16B) per thread
    const int lrow = tid >> 2, lcg = tid & 3;
    auto load_stage = [&](int s, int kt) {
        const uint32_t base = tiles_u32 + s * STAGE_BYTES;
        cp16(base + lrow * 64 + lcg * 16,
             A + (size_t)(m0 + lrow) * K + kt * BK + lcg * 4);
        cp16(base + 8192 + lrow * 64 + lcg * 16,
             Bt + (size_t)(n0 + lrow) * K + kt * BK + lcg * 4);
    };

    #pragma unroll
    for (int s = 0; s < STAGES - 1; s++) { load_stage(s, s); CP_COMMIT(); }

    float acc[2][4][4];
    #pragma unroll
    for (int im = 0; im < 2; im++)
        #pragma unroll
        for (int in = 0; in < 4; in++)
            #pragma unroll
            for (int q = 0; q < 4; q++) acc[im][in][q] = 0.f;

    for (int kt = 0; kt < KT; kt++) {
        CP_WAIT(STAGES - 2);
        __syncthreads();

        const int kn = kt + STAGES - 1;
        if (kn < KT) load_stage(kn & (STAGES - 1), kn);
        CP_COMMIT();

        const float4* As4 = (const float4*)(smem + SMEM_TILES + (kt & (STAGES - 1)) * STAGE_BYTES);
        const float4* Bs4 = As4 + 512;

        // one float4 per row/col covers both k-steps (K-permuted layout)
        float4 a[2][2], b[4];
        #pragma unroll
        for (int im = 0; im < 2; im++)
            #pragma unroll
            for (int h = 0; h < 2; h++)
                a[im][h] = As4[(wm * 32 + im * 16 + h * 8 + g) * 4 + tg];
        #pragma unroll
        for (int in = 0; in < 4; in++)
            b[in] = Bs4[(wn * 32 + in * 8 + g) * 4 + tg];

        #pragma unroll
        for (int im = 0; im < 2; im++)
            #pragma unroll
            for (int in = 0; in < 4; in++) {
                // ks = 0: k = tg, tg+4
                mma_tf32(acc[im][in],
                         __float_as_uint(a[im][0].x), __float_as_uint(a[im][1].x),
                         __float_as_uint(a[im][0].y), __float_as_uint(a[im][1].y),
                         __float_as_uint(b[in].x),    __float_as_uint(b[in].y));
                // ks = 1: k = 8+tg, 12+tg
                mma_tf32(acc[im][in],
                         __float_as_uint(a[im][0].z), __float_as_uint(a[im][1].z),
                         __float_as_uint(a[im][0].w), __float_as_uint(a[im][1].w),
                         __float_as_uint(b[in].z),    __float_as_uint(b[in].w));
            }
        __syncthreads();
    }

    // -------- epilogue -----------------------------------------------------
    #pragma unroll
    for (int im = 0; im < 2; im++) {
        #pragma unroll
        for (int in = 0; in < 4; in++) {
            const int cl = wn * 32 + in * 8 + 2 * tg;
            #pragma unroll
            for (int h = 0; h < 2; h++) {
                const int row = m0 + wm * 32 + im * 16 + g + 8 * h;
                float v0 = acc[im][in][2 * h]     + bias_s[cl];
                float v1 = acc[im][in][2 * h + 1] + bias_s[cl + 1];
                if (ACT == 0) {
                    v0 = tf32_round(fmaxf(v0, 0.f));
                    v1 = tf32_round(fmaxf(v1, 0.f));
                    // K-permuted scalar stores for the next GEMM
                    const int c0 = n0 + cl;
                    const int b0 = c0 & ~15;
                    C[(size_t)row * N + b0 + kperm(c0 & 15)]       = v0;
                    C[(size_t)row * N + b0 + kperm((c0 + 1) & 15)] = v1;
                } else {
                    v0 = 1.f / (1.f + __expf(-v0));
                    v1 = 1.f / (1.f + __expf(-v1));
                    *(float2*)(C + (size_t)row * N + n0 + cl) = make_float2(v0, v1);
                }
            }
        }
    }
}

// ---------------------------------------------------------------------------
// Kernel A: capsule argmax mask + FC1 (effective K=16) + ReLU,
// tf32-rounded, K-permuted store.
// ---------------------------------------------------------------------------
__global__ void mask_fc1_kernel(const float* __restrict__ x,
                                const float* __restrict__ W1,
                                const float* __restrict__ b1)
{
    __shared__ float xs[D_IN];
    __shared__ float n2[10];
    __shared__ int   jm;

    const int b = blockIdx.x;
    const float* xr = x + (size_t)b * D_IN;

    for (int i = threadIdx.x; i < D_IN; i += blockDim.x) xs[i] = xr[i];
    __syncthreads();

    if (threadIdx.x < 10) {
        float s = 0.f;
        #pragma unroll
        for (int u = 0; u < 16; u++) { float v = xs[threadIdx.x * 16 + u]; s += v * v; }
        n2[threadIdx.x] = s;
    }
    __syncthreads();
    if (threadIdx.x == 0) {
        int best = 0; float bv = n2[0];
        #pragma unroll
        for (int j = 1; j < 10; j++) if (n2[j] > bv) { bv = n2[j]; best = j; }
        jm = best;
    }
    __syncthreads();

    const int base = jm * 16;
    for (int c = threadIdx.x; c < D_H1; c += blockDim.x) {
        float acc = b1[c];
        #pragma unroll
        for (int u = 0; u < 16; u++)
            acc += xs[base + u] * W1[(size_t)(base + u) * D_H1 + c];
        g_h1[(size_t)b * D_H1 + (c & ~15) + kperm(c & 15)] = tf32_round(fmaxf(acc, 0.f));
    }
}

// ---------------------------------------------------------------------------
// Transpose + tf32-round + K-perm:  W [K,N] -> Wt [N,K] (K-permuted)
// grid (N/32, K/32), block (32, 8)
// ---------------------------------------------------------------------------
__global__ void transpose_kernel(const float* __restrict__ W, float* __restrict__ Wt,
                                 int K, int N)
{
    __shared__ float t[32][33];
    const int k0 = blockIdx.y * 32, n0 = blockIdx.x * 32;
    #pragma unroll
    for (int j = 0; j < 4; j++) {
        int k = threadIdx.y + j * 8;
        t[k][threadIdx.x] = W[(size_t)(k0 + k) * N + n0 + threadIdx.x];
    }
    __syncthreads();
    #pragma unroll
    for (int j = 0; j < 4; j++) {
        int n = threadIdx.y + j * 8;
        int kk = k0 + threadIdx.x;
        Wt[(size_t)(n0 + n) * K + (kk & ~15) + kperm(kk & 15)] =
            tf32_round(t[threadIdx.x][n]);
    }
}

// ---------------------------------------------------------------------------
extern "C" void kernel_launch(void* const* d_in, const int* in_sizes, int n_in,
                              void* d_out, int out_size)
{
    const float* x  = (const float*)d_in[0];
    const float* W1 = (const float*)d_in[2];
    const float* b1 = (const float*)d_in[3];
    const float* W2 = (const float*)d_in[4];
    const float* b2 = (const float*)d_in[5];
    const float* W3 = (const float*)d_in[6];
    const float* b3 = (const float*)d_in[7];
    float* out = (float*)d_out;

    float *h1, *h2, *w2t, *w3t;
    cudaGetSymbolAddress((void**)&h1,  g_h1);
    cudaGetSymbolAddress((void**)&h2,  g_h2);
    cudaGetSymbolAddress((void**)&w2t, g_w2t);
    cudaGetSymbolAddress((void**)&w3t, g_w3t);

    cudaFuncSetAttribute(gemm_mma<0>, cudaFuncAttributeMaxDynamicSharedMemorySize, SMEM_DYN);
    cudaFuncSetAttribute(gemm_mma<1>, cudaFuncAttributeMaxDynamicSharedMemorySize, SMEM_DYN);

    transpose_kernel<<<dim3(D_H2 / 32, D_H1 / 32), dim3(32, 8)>>>(W2, w2t, D_H1, D_H2);
    transpose_kernel<<<dim3(D_OUT / 32, D_H2 / 32), dim3(32, 8)>>>(W3, w3t, D_H2, D_OUT);

    mask_fc1_kernel<<<BATCH, 128>>>(x, W1, b1);

    gemm_mma<0><<<(BATCH / BM) * (D_H2 / BN), 512, SMEM_DYN>>>(
        h1, w2t, b2, h2, BATCH, D_H2, D_H1);

    gemm_mma<1><<<(BATCH / BM) * (D_OUT / BN), 512, SMEM_DYN>>>(
        h2, w3t, b3, out, BATCH, D_OUT, D_H2);
}

// round 5
// speedup vs baseline: 1.3395x; 1.3395x over previous
#include <cuda_runtime.h>
#include <cstdint>

#define BATCH   32768
#define D_IN    160
#define D_H1    512
#define D_H2    1024
#define D_OUT   3072

// ---------------- scratch (static device arrays; allocation-free) -----------
// All GEMM operands stored K-permuted: within each 16-float K block, element k
// lives at position p = (k%4)*4 + k/4  (so p = 4*tg+j holds k = 4*j+tg).
__device__ float g_h1[BATCH * D_H1];    //  64 MB
__device__ float g_h2[BATCH * D_H2];    // 128 MB
__device__ float g_w2t[D_H2 * D_H1];    //   2 MB  W2^T [1024,512]
__device__ float g_w3t[D_OUT * D_H2];   //  12 MB  W3^T [3072,1024]

// ---------------- helpers ---------------------------------------------------
__device__ __forceinline__ uint32_t smem_u32(const void* p) {
    uint32_t a;
    asm("{ .reg .u64 t; cvta.to.shared.u64 t, %1; cvt.u32.u64 %0, t; }" : "=r"(a) : "l"(p));
    return a;
}
__device__ __forceinline__ float tf32_round(float v) {
    uint32_t o;
    asm("cvt.rna.tf32.f32 %0, %1;" : "=r"(o) : "f"(v));
    return __uint_as_float(o);
}
__device__ __forceinline__ int kperm(int j) { return (j & 3) * 4 + (j >> 2); }  // j in [0,16)

__device__ __forceinline__ void cp16(uint32_t dst, const void* src) {
    asm volatile("cp.async.cg.shared.global [%0], [%1], 16;" :: "r"(dst), "l"(src));
}
#define CP_COMMIT()  asm volatile("cp.async.commit_group;" ::: "memory")
#define CP_WAIT(n)   asm volatile("cp.async.wait_group %0;" :: "n"(n) : "memory")

__device__ __forceinline__ void mma_tf32(float* c,
                                         uint32_t a0, uint32_t a1, uint32_t a2, uint32_t a3,
                                         uint32_t b0, uint32_t b1) {
    asm volatile(
        "mma.sync.aligned.m16n8k8.row.col.f32.tf32.tf32.f32 "
        "{%0,%1,%2,%3}, {%4,%5,%6,%7}, {%8,%9}, {%0,%1,%2,%3};"
        : "+f"(c[0]), "+f"(c[1]), "+f"(c[2]), "+f"(c[3])
        : "r"(a0), "r"(a1), "r"(a2), "r"(a3), "r"(b0), "r"(b1));
}

// ---------------- GEMM config ----------------------------------------------
#define BM 128
#define BN 128
#define BK 16
#define STAGES 4
#define STAGE_BYTES (2 * BM * BK * 4)              // 16384 (A 8K + B 8K)
#define SMEM_BIAS   0
#define SMEM_TILES  1024
#define SMEM_DYN    (SMEM_TILES + STAGES * STAGE_BYTES)   // 66560 -> 2 CTAs/SM
#define GROUP_M 16

// ---------------------------------------------------------------------------
// Pipelined tf32 mma.sync GEMM:  C[M,N] = act(A[M,K] @ Bt[N,K]^T + bias)
// A [M,K], Bt [N,K], row-major, tf32-rounded, K-permuted per 16-block.
// 256 threads, 8 warps (4x2), warp tile 32x64, 4-stage cp.async pipeline,
// ONE barrier per K-tile.
// ACT: 0 = relu + tf32 round + K-permuted store (feeds next GEMM)
//      1 = sigmoid, plain row-major float2 stores
// ---------------------------------------------------------------------------
template <int ACT>
__global__ __launch_bounds__(256, 2)
void gemm_mma(const float* __restrict__ A, const float* __restrict__ Bt,
              const float* __restrict__ bias, float* __restrict__ C,
              int M, int N, int K)
{
    extern __shared__ char smem[];
    float* bias_s = (float*)(smem + SMEM_BIAS);
    const uint32_t tiles_u32 = smem_u32(smem + SMEM_TILES);

    const int tid  = threadIdx.x;
    const int wid  = tid >> 5, lane = tid & 31;
    const int g    = lane >> 2, tg = lane & 3;
    const int wm   = wid & 3, wn = wid >> 2;          // 4 x 2 warp grid

    // grouped rasterization
    const int num_n = N / BN;
    const int tpg   = GROUP_M * num_n;
    const int grp   = blockIdx.x / tpg;
    const int rem   = blockIdx.x % tpg;
    const int m0 = (grp * GROUP_M + rem % GROUP_M) * BM;
    const int n0 = (rem / GROUP_M) * BN;

    if (tid < BN) bias_s[tid] = bias[n0 + tid];

    const int KT = K / BK;

    // stage loader: 2 A + 2 B 16B chunks per thread
    auto load_stage = [&](int s, int kt) {
        const uint32_t base = tiles_u32 + s * STAGE_BYTES;
        #pragma unroll
        for (int j = 0; j < 2; j++) {
            const int q = tid + j * 256;              // 0..511
            const int row = q >> 2, cg = q & 3;
            cp16(base + row * 64 + cg * 16,
                 A + (size_t)(m0 + row) * K + kt * BK + cg * 4);
            cp16(base + 8192 + row * 64 + cg * 16,
                 Bt + (size_t)(n0 + row) * K + kt * BK + cg * 4);
        }
    };

    #pragma unroll
    for (int s = 0; s < STAGES - 1; s++) { load_stage(s, s); CP_COMMIT(); }

    float acc[2][8][4];
    #pragma unroll
    for (int im = 0; im < 2; im++)
        #pragma unroll
        for (int in = 0; in < 8; in++)
            #pragma unroll
            for (int q = 0; q < 4; q++) acc[im][in][q] = 0.f;

    for (int kt = 0; kt < KT; kt++) {
        CP_WAIT(STAGES - 2);
        __syncthreads();     // stage kt ready; also orders prev-iter reads
                             // before this iter's prefetch overwrite

        const int kn = kt + STAGES - 1;
        if (kn < KT) load_stage(kn & (STAGES - 1), kn);
        CP_COMMIT();

        const float4* As4 = (const float4*)(smem + SMEM_TILES + (kt & (STAGES - 1)) * STAGE_BYTES);
        const float4* Bs4 = As4 + 512;

        // one float4 per row/col covers both k-steps (K-permuted layout)
        float4 a[2][2];
        #pragma unroll
        for (int im = 0; im < 2; im++)
            #pragma unroll
            for (int h = 0; h < 2; h++)
                a[im][h] = As4[(wm * 32 + im * 16 + h * 8 + g) * 4 + tg];

        #pragma unroll
        for (int half = 0; half < 2; half++) {
            float4 b[4];
            #pragma unroll
            for (int i = 0; i < 4; i++)
                b[i] = Bs4[(wn * 64 + half * 32 + i * 8 + g) * 4 + tg];
            #pragma unroll
            for (int im = 0; im < 2; im++)
                #pragma unroll
                for (int i = 0; i < 4; i++) {
                    float* c = acc[im][half * 4 + i];
                    // ks = 0: k = tg, tg+4
                    mma_tf32(c,
                             __float_as_uint(a[im][0].x), __float_as_uint(a[im][1].x),
                             __float_as_uint(a[im][0].y), __float_as_uint(a[im][1].y),
                             __float_as_uint(b[i].x),     __float_as_uint(b[i].y));
                    // ks = 1: k = 8+tg, 12+tg
                    mma_tf32(c,
                             __float_as_uint(a[im][0].z), __float_as_uint(a[im][1].z),
                             __float_as_uint(a[im][0].w), __float_as_uint(a[im][1].w),
                             __float_as_uint(b[i].z),     __float_as_uint(b[i].w));
                }
        }
    }

    // -------- epilogue -----------------------------------------------------
    #pragma unroll
    for (int im = 0; im < 2; im++) {
        #pragma unroll
        for (int in = 0; in < 8; in++) {
            const int cl = wn * 64 + in * 8 + 2 * tg;
            #pragma unroll
            for (int h = 0; h < 2; h++) {
                const int row = m0 + wm * 32 + im * 16 + g + 8 * h;
                float v0 = acc[im][in][2 * h]     + bias_s[cl];
                float v1 = acc[im][in][2 * h + 1] + bias_s[cl + 1];
                if (ACT == 0) {
                    v0 = tf32_round(fmaxf(v0, 0.f));
                    v1 = tf32_round(fmaxf(v1, 0.f));
                    // K-permuted scalar stores for the next GEMM
                    const int c0 = n0 + cl;
                    const int b0 = c0 & ~15;
                    C[(size_t)row * N + b0 + kperm(c0 & 15)]       = v0;
                    C[(size_t)row * N + b0 + kperm((c0 + 1) & 15)] = v1;
                } else {
                    v0 = 1.f / (1.f + __expf(-v0));
                    v1 = 1.f / (1.f + __expf(-v1));
                    *(float2*)(C + (size_t)row * N + n0 + cl) = make_float2(v0, v1);
                }
            }
        }
    }
}

// ---------------------------------------------------------------------------
// Kernel A: capsule argmax mask + FC1 (effective K=16) + ReLU,
// tf32-rounded, K-permuted store.
// ---------------------------------------------------------------------------
__global__ void mask_fc1_kernel(const float* __restrict__ x,
                                const float* __restrict__ W1,
                                const float* __restrict__ b1)
{
    __shared__ float xs[D_IN];
    __shared__ float n2[10];
    __shared__ int   jm;

    const int b = blockIdx.x;
    const float* xr = x + (size_t)b * D_IN;

    for (int i = threadIdx.x; i < D_IN; i += blockDim.x) xs[i] = xr[i];
    __syncthreads();

    if (threadIdx.x < 10) {
        float s = 0.f;
        #pragma unroll
        for (int u = 0; u < 16; u++) { float v = xs[threadIdx.x * 16 + u]; s += v * v; }
        n2[threadIdx.x] = s;
    }
    __syncthreads();
    if (threadIdx.x == 0) {
        int best = 0; float bv = n2[0];
        #pragma unroll
        for (int j = 1; j < 10; j++) if (n2[j] > bv) { bv = n2[j]; best = j; }
        jm = best;
    }
    __syncthreads();

    const int base = jm * 16;
    for (int c = threadIdx.x; c < D_H1; c += blockDim.x) {
        float acc = b1[c];
        #pragma unroll
        for (int u = 0; u < 16; u++)
            acc += xs[base + u] * W1[(size_t)(base + u) * D_H1 + c];
        g_h1[(size_t)b * D_H1 + (c & ~15) + kperm(c & 15)] = tf32_round(fmaxf(acc, 0.f));
    }
}

// ---------------------------------------------------------------------------
// Transpose + tf32-round + K-perm:  W [K,N] -> Wt [N,K] (K-permuted)
// grid (N/32, K/32), block (32, 8)
// ---------------------------------------------------------------------------
__global__ void transpose_kernel(const float* __restrict__ W, float* __restrict__ Wt,
                                 int K, int N)
{
    __shared__ float t[32][33];
    const int k0 = blockIdx.y * 32, n0 = blockIdx.x * 32;
    #pragma unroll
    for (int j = 0; j < 4; j++) {
        int k = threadIdx.y + j * 8;
        t[k][threadIdx.x] = W[(size_t)(k0 + k) * N + n0 + threadIdx.x];
    }
    __syncthreads();
    #pragma unroll
    for (int j = 0; j < 4; j++) {
        int n = threadIdx.y + j * 8;
        int kk = k0 + threadIdx.x;
        Wt[(size_t)(n0 + n) * K + (kk & ~15) + kperm(kk & 15)] =
            tf32_round(t[threadIdx.x][n]);
    }
}

// ---------------------------------------------------------------------------
extern "C" void kernel_launch(void* const* d_in, const int* in_sizes, int n_in,
                              void* d_out, int out_size)
{
    const float* x  = (const float*)d_in[0];
    const float* W1 = (const float*)d_in[2];
    const float* b1 = (const float*)d_in[3];
    const float* W2 = (const float*)d_in[4];
    const float* b2 = (const float*)d_in[5];
    const float* W3 = (const float*)d_in[6];
    const float* b3 = (const float*)d_in[7];
    float* out = (float*)d_out;

    float *h1, *h2, *w2t, *w3t;
    cudaGetSymbolAddress((void**)&h1,  g_h1);
    cudaGetSymbolAddress((void**)&h2,  g_h2);
    cudaGetSymbolAddress((void**)&w2t, g_w2t);
    cudaGetSymbolAddress((void**)&w3t, g_w3t);

    cudaFuncSetAttribute(gemm_mma<0>, cudaFuncAttributeMaxDynamicSharedMemorySize, SMEM_DYN);
    cudaFuncSetAttribute(gemm_mma<1>, cudaFuncAttributeMaxDynamicSharedMemorySize, SMEM_DYN);

    transpose_kernel<<<dim3(D_H2 / 32, D_H1 / 32), dim3(32, 8)>>>(W2, w2t, D_H1, D_H2);
    transpose_kernel<<<dim3(D_OUT / 32, D_H2 / 32), dim3(32, 8)>>>(W3, w3t, D_H2, D_OUT);

    mask_fc1_kernel<<<BATCH, 128>>>(x, W1, b1);

    gemm_mma<0><<<(BATCH / BM) * (D_H2 / BN), 256, SMEM_DYN>>>(
        h1, w2t, b2, h2, BATCH, D_H2, D_H1);

    gemm_mma<1><<<(BATCH / BM) * (D_OUT / BN), 256, SMEM_DYN>>>(
        h2, w3t, b3, out, BATCH, D_OUT, D_H2);
}

// round 6
// speedup vs baseline: 2.3863x; 1.7815x over previous
#include <cuda_runtime.h>
#include <cuda_bf16.h>
#include <cstdint>

#define BATCH   32768
#define D_IN    160
#define D_H1    512
#define D_H2    1024
#define D_OUT   3072

// ---------------- scratch (static device arrays; allocation-free) -----------
// GEMM operands in bf16, K-permuted per 32-element block:
// element k lives at pos = ((k>>1)&3)*8 + ((k>>3)<<1) + (k&1), so thread tg's
// 16B chunk holds k = {2tg,2tg+1, 8+2tg,8+2tg+1, 16+2tg,16+2tg+1, 24+2tg,24+2tg+1}.
__device__ __nv_bfloat16 g_h1[BATCH * D_H1];    // 32 MB
__device__ __nv_bfloat16 g_h2[BATCH * D_H2];    // 64 MB
__device__ __nv_bfloat16 g_w2t[D_H2 * D_H1];    //  1 MB  W2^T [1024,512]
__device__ __nv_bfloat16 g_w3t[D_OUT * D_H2];   //  6 MB  W3^T [3072,1024]

// ---------------- helpers ---------------------------------------------------
__device__ __forceinline__ uint32_t smem_u32(const void* p) {
    uint32_t a;
    asm("{ .reg .u64 t; cvta.to.shared.u64 t, %1; cvt.u32.u64 %0, t; }" : "=r"(a) : "l"(p));
    return a;
}
__device__ __forceinline__ int kperm32(int k) {           // k in [0,32)
    return ((k >> 1) & 3) * 8 + ((k >> 3) << 1) + (k & 1);
}
__device__ __forceinline__ void cp16(uint32_t dst, const void* src) {
    asm volatile("cp.async.cg.shared.global [%0], [%1], 16;" :: "r"(dst), "l"(src));
}
#define CP_COMMIT()  asm volatile("cp.async.commit_group;" ::: "memory")
#define CP_WAIT(n)   asm volatile("cp.async.wait_group %0;" :: "n"(n) : "memory")

__device__ __forceinline__ void mma_bf16(float* c,
                                         uint32_t a0, uint32_t a1, uint32_t a2, uint32_t a3,
                                         uint32_t b0, uint32_t b1) {
    asm volatile(
        "mma.sync.aligned.m16n8k16.row.col.f32.bf16.bf16.f32 "
        "{%0,%1,%2,%3}, {%4,%5,%6,%7}, {%8,%9}, {%0,%1,%2,%3};"
        : "+f"(c[0]), "+f"(c[1]), "+f"(c[2]), "+f"(c[3])
        : "r"(a0), "r"(a1), "r"(a2), "r"(a3), "r"(b0), "r"(b1));
}

// ---------------- GEMM config ----------------------------------------------
#define BM 128
#define BN 128
#define BK 32
#define STAGES 4
#define STAGE_BYTES (2 * BM * BK * 2)              // 16384 (A 8K + B 8K)
#define SMEM_BIAS   0
#define SMEM_TILES  1024
#define SMEM_DYN    (SMEM_TILES + STAGES * STAGE_BYTES)   // 66560 -> 2 CTAs/SM
#define GROUP_M 16

// ---------------------------------------------------------------------------
// Pipelined bf16 mma.sync GEMM:  C[M,N] = act(A[M,K] @ Bt[N,K]^T + bias)
// A [M,K], Bt [N,K] bf16, row-major, K-permuted per 32-block.
// 256 threads, 8 warps (4x2), warp tile 32x64, 4-stage cp.async pipeline,
// one barrier per K-tile, fp32 accumulate.
// ACT: 0 = relu, bf16 K-permuted stores (feeds next GEMM)
//      1 = sigmoid, fp32 row-major float2 stores
// ---------------------------------------------------------------------------
template <int ACT>
__global__ __launch_bounds__(256, 2)
void gemm_bf16(const __nv_bfloat16* __restrict__ A, const __nv_bfloat16* __restrict__ Bt,
               const float* __restrict__ bias, void* __restrict__ Cv,
               int M, int N, int K)
{
    extern __shared__ char smem[];
    float* bias_s = (float*)(smem + SMEM_BIAS);
    const uint32_t tiles_u32 = smem_u32(smem + SMEM_TILES);

    const int tid  = threadIdx.x;
    const int wid  = tid >> 5, lane = tid & 31;
    const int g    = lane >> 2, tg = lane & 3;
    const int wm   = wid & 3, wn = wid >> 2;          // 4 x 2 warp grid

    // grouped rasterization
    const int num_n = N / BN;
    const int tpg   = GROUP_M * num_n;
    const int grp   = blockIdx.x / tpg;
    const int rem   = blockIdx.x % tpg;
    const int m0 = (grp * GROUP_M + rem % GROUP_M) * BM;
    const int n0 = (rem / GROUP_M) * BN;

    if (tid < BN) bias_s[tid] = bias[n0 + tid];

    const int KT = K / BK;

    // stage loader: 2 A + 2 B 16B chunks per thread (rows are 64B = 4 chunks)
    auto load_stage = [&](int s, int kt) {
        const uint32_t base = tiles_u32 + s * STAGE_BYTES;
        #pragma unroll
        for (int j = 0; j < 2; j++) {
            const int q = tid + j * 256;              // 0..511
            const int row = q >> 2, cg = q & 3;
            cp16(base + row * 64 + cg * 16,
                 A + (size_t)(m0 + row) * K + kt * BK + cg * 8);
            cp16(base + 8192 + row * 64 + cg * 16,
                 Bt + (size_t)(n0 + row) * K + kt * BK + cg * 8);
        }
    };

    #pragma unroll
    for (int s = 0; s < STAGES - 1; s++) { load_stage(s, s); CP_COMMIT(); }

    float acc[2][8][4];
    #pragma unroll
    for (int im = 0; im < 2; im++)
        #pragma unroll
        for (int in = 0; in < 8; in++)
            #pragma unroll
            for (int q = 0; q < 4; q++) acc[im][in][q] = 0.f;

    for (int kt = 0; kt < KT; kt++) {
        CP_WAIT(STAGES - 2);
        __syncthreads();     // stage kt ready; orders prev reads before overwrite

        const int kn = kt + STAGES - 1;
        if (kn < KT) load_stage(kn & (STAGES - 1), kn);
        CP_COMMIT();

        const uint4* As4 = (const uint4*)(smem + SMEM_TILES + (kt & (STAGES - 1)) * STAGE_BYTES);
        const uint4* Bs4 = As4 + 512;

        // one uint4 per row/col covers both k16 MMA steps (K-perm layout)
        uint4 a[2][2];
        #pragma unroll
        for (int im = 0; im < 2; im++)
            #pragma unroll
            for (int h = 0; h < 2; h++)
                a[im][h] = As4[(wm * 32 + im * 16 + h * 8 + g) * 4 + tg];

        #pragma unroll
        for (int half = 0; half < 2; half++) {
            uint4 b[4];
            #pragma unroll
            for (int i = 0; i < 4; i++)
                b[i] = Bs4[(wn * 64 + half * 32 + i * 8 + g) * 4 + tg];
            #pragma unroll
            for (int im = 0; im < 2; im++)
                #pragma unroll
                for (int i = 0; i < 4; i++) {
                    float* c = acc[im][half * 4 + i];
                    // k[0:16)
                    mma_bf16(c, a[im][0].x, a[im][1].x, a[im][0].y, a[im][1].y,
                             b[i].x, b[i].y);
                    // k[16:32)
                    mma_bf16(c, a[im][0].z, a[im][1].z, a[im][0].w, a[im][1].w,
                             b[i].z, b[i].w);
                }
        }
    }

    // -------- epilogue -----------------------------------------------------
    #pragma unroll
    for (int im = 0; im < 2; im++) {
        #pragma unroll
        for (int in = 0; in < 8; in++) {
            const int cl = wn * 64 + in * 8 + 2 * tg;
            #pragma unroll
            for (int h = 0; h < 2; h++) {
                const int row = m0 + wm * 32 + im * 16 + g + 8 * h;
                float v0 = acc[im][in][2 * h]     + bias_s[cl];
                float v1 = acc[im][in][2 * h + 1] + bias_s[cl + 1];
                if (ACT == 0) {
                    v0 = fmaxf(v0, 0.f);
                    v1 = fmaxf(v1, 0.f);
                    const int c0 = n0 + cl;                     // even
                    const int kk = c0 & 31;
                    const int pos = (c0 & ~31) + ((kk >> 1) & 3) * 8 + ((kk >> 3) << 1);
                    *(__nv_bfloat162*)((__nv_bfloat16*)Cv + (size_t)row * N + pos) =
                        __floats2bfloat162_rn(v0, v1);
                } else {
                    v0 = 1.f / (1.f + __expf(-v0));
                    v1 = 1.f / (1.f + __expf(-v1));
                    *(float2*)((float*)Cv + (size_t)row * N + n0 + cl) =
                        make_float2(v0, v1);
                }
            }
        }
    }
}

// ---------------------------------------------------------------------------
// Kernel A: capsule argmax mask + FC1 (effective K=16, fp32) + ReLU,
// bf16 K-permuted store.
// ---------------------------------------------------------------------------
__global__ void mask_fc1_kernel(const float* __restrict__ x,
                                const float* __restrict__ W1,
                                const float* __restrict__ b1)
{
    __shared__ float xs[D_IN];
    __shared__ float n2[10];
    __shared__ int   jm;

    const int b = blockIdx.x;
    const float* xr = x + (size_t)b * D_IN;

    for (int i = threadIdx.x; i < D_IN; i += blockDim.x) xs[i] = xr[i];
    __syncthreads();

    if (threadIdx.x < 10) {
        float s = 0.f;
        #pragma unroll
        for (int u = 0; u < 16; u++) { float v = xs[threadIdx.x * 16 + u]; s += v * v; }
        n2[threadIdx.x] = s;
    }
    __syncthreads();
    if (threadIdx.x == 0) {
        int best = 0; float bv = n2[0];
        #pragma unroll
        for (int j = 1; j < 10; j++) if (n2[j] > bv) { bv = n2[j]; best = j; }
        jm = best;
    }
    __syncthreads();

    const int base = jm * 16;
    for (int c = threadIdx.x; c < D_H1; c += blockDim.x) {
        float acc = b1[c];
        #pragma unroll
        for (int u = 0; u < 16; u++)
            acc += xs[base + u] * W1[(size_t)(base + u) * D_H1 + c];
        g_h1[(size_t)b * D_H1 + (c & ~31) + kperm32(c & 31)] =
            __float2bfloat16_rn(fmaxf(acc, 0.f));
    }
}

// ---------------------------------------------------------------------------
// Transpose + bf16 + K-perm:  W [K,N] fp32 -> Wt [N,K] bf16 (K-perm32)
// grid (N/32, K/32), block (32, 8)
// ---------------------------------------------------------------------------
__global__ void transpose_kernel(const float* __restrict__ W, __nv_bfloat16* __restrict__ Wt,
                                 int K, int N)
{
    __shared__ float t[32][33];
    const int k0 = blockIdx.y * 32, n0 = blockIdx.x * 32;
    #pragma unroll
    for (int j = 0; j < 4; j++) {
        int k = threadIdx.y + j * 8;
        t[k][threadIdx.x] = W[(size_t)(k0 + k) * N + n0 + threadIdx.x];
    }
    __syncthreads();
    #pragma unroll
    for (int j = 0; j < 4; j++) {
        int n = threadIdx.y + j * 8;
        int kk = k0 + threadIdx.x;
        Wt[(size_t)(n0 + n) * K + (kk & ~31) + kperm32(kk & 31)] =
            __float2bfloat16_rn(t[threadIdx.x][n]);
    }
}

// ---------------------------------------------------------------------------
extern "C" void kernel_launch(void* const* d_in, const int* in_sizes, int n_in,
                              void* d_out, int out_size)
{
    const float* x  = (const float*)d_in[0];
    const float* W1 = (const float*)d_in[2];
    const float* b1 = (const float*)d_in[3];
    const float* W2 = (const float*)d_in[4];
    const float* b2 = (const float*)d_in[5];
    const float* W3 = (const float*)d_in[6];
    const float* b3 = (const float*)d_in[7];
    float* out = (float*)d_out;

    __nv_bfloat16 *h1, *h2, *w2t, *w3t;
    cudaGetSymbolAddress((void**)&h1,  g_h1);
    cudaGetSymbolAddress((void**)&h2,  g_h2);
    cudaGetSymbolAddress((void**)&w2t, g_w2t);
    cudaGetSymbolAddress((void**)&w3t, g_w3t);

    cudaFuncSetAttribute(gemm_bf16<0>, cudaFuncAttributeMaxDynamicSharedMemorySize, SMEM_DYN);
    cudaFuncSetAttribute(gemm_bf16<1>, cudaFuncAttributeMaxDynamicSharedMemorySize, SMEM_DYN);

    transpose_kernel<<<dim3(D_H2 / 32, D_H1 / 32), dim3(32, 8)>>>(W2, w2t, D_H1, D_H2);
    transpose_kernel<<<dim3(D_OUT / 32, D_H2 / 32), dim3(32, 8)>>>(W3, w3t, D_H2, D_OUT);

    mask_fc1_kernel<<<BATCH, 128>>>(x, W1, b1);

    // h2 = relu(h1 @ W2 + b2), bf16 K-permuted
    gemm_bf16<0><<<(BATCH / BM) * (D_H2 / BN), 256, SMEM_DYN>>>(
        h1, w2t, b2, h2, BATCH, D_H2, D_H1);

    // out = sigmoid(h2 @ W3 + b3), fp32
    gemm_bf16<1><<<(BATCH / BM) * (D_OUT / BN), 256, SMEM_DYN>>>(
        h2, w3t, b3, out, BATCH, D_OUT, D_H2);
}

// round 8
// speedup vs baseline: 2.4121x; 1.0108x over previous
#include <cuda_runtime.h>
#include <cuda_bf16.h>
#include <cstdint>

#define BATCH   32768
#define D_IN    160
#define D_H1    512
#define D_H2    1024
#define D_OUT   3072

// ---------------- scratch (static device arrays; allocation-free) -----------
// GEMM operands in bf16, K-permuted per 32-element block:
// element k lives at pos = ((k>>1)&3)*8 + ((k>>3)<<1) + (k&1), so thread tg's
// 16B chunk holds k = {2tg,2tg+1, 8+2tg,8+2tg+1, 16+2tg,16+2tg+1, 24+2tg,24+2tg+1}.
__device__ __nv_bfloat16 g_h1[BATCH * D_H1];    // 32 MB
__device__ __nv_bfloat16 g_h2[BATCH * D_H2];    // 64 MB
__device__ __nv_bfloat16 g_w2t[D_H2 * D_H1];    //  1 MB  W2^T [1024,512]
__device__ __nv_bfloat16 g_w3t[D_OUT * D_H2];   //  6 MB  W3^T [3072,1024]

// ---------------- helpers ---------------------------------------------------
__device__ __forceinline__ uint32_t smem_u32(const void* p) {
    uint32_t a;
    asm("{ .reg .u64 t; cvta.to.shared.u64 t, %1; cvt.u32.u64 %0, t; }" : "=r"(a) : "l"(p));
    return a;
}
__device__ __forceinline__ int kperm32(int k) {           // k in [0,32)
    return ((k >> 1) & 3) * 8 + ((k >> 3) << 1) + (k & 1);
}
__device__ __forceinline__ void cp16(uint32_t dst, const void* src) {
    asm volatile("cp.async.cg.shared.global [%0], [%1], 16;" :: "r"(dst), "l"(src));
}
#define CP_COMMIT()  asm volatile("cp.async.commit_group;" ::: "memory")
#define CP_WAIT(n)   asm volatile("cp.async.wait_group %0;" :: "n"(n) : "memory")

__device__ __forceinline__ void mma_bf16(float* c,
                                         uint32_t a0, uint32_t a1, uint32_t a2, uint32_t a3,
                                         uint32_t b0, uint32_t b1) {
    asm volatile(
        "mma.sync.aligned.m16n8k16.row.col.f32.bf16.bf16.f32 "
        "{%0,%1,%2,%3}, {%4,%5,%6,%7}, {%8,%9}, {%0,%1,%2,%3};"
        : "+f"(c[0]), "+f"(c[1]), "+f"(c[2]), "+f"(c[3])
        : "r"(a0), "r"(a1), "r"(a2), "r"(a3), "r"(b0), "r"(b1));
}

// ---------------- GEMM config ----------------------------------------------
#define BM 128
#define BN 128
#define BK 32
#define STAGES 6
#define STAGE_BYTES (2 * BM * BK * 2)              // 16384 (A 8K + B 8K)
#define SMEM_BIAS   0
#define SMEM_TILES  1024
#define SMEM_DYN    (SMEM_TILES + STAGES * STAGE_BYTES)   // 99328 -> 2 CTAs/SM
#define GROUP_M 16

// ---------------------------------------------------------------------------
// Pipelined bf16 mma.sync GEMM:  C[M,N] = act(A[M,K] @ Bt[N,K]^T + bias)
// A [M,K], Bt [N,K] bf16, row-major, K-permuted per 32-block.
// 128 threads, 4 warps (2x2), warp tile 64x64, 6-stage cp.async pipeline,
// one barrier per K-tile, fp32 accumulate, 2 CTAs/SM.
// Stage indices tracked with explicit wrap counters (STAGES=6 is not pow2!).
// ACT: 0 = relu, bf16 K-permuted stores (feeds next GEMM)
//      1 = sigmoid, fp32 row-major float2 stores
// ---------------------------------------------------------------------------
template <int ACT>
__global__ __launch_bounds__(128, 2)
void gemm_bf16(const __nv_bfloat16* __restrict__ A, const __nv_bfloat16* __restrict__ Bt,
               const float* __restrict__ bias, void* __restrict__ Cv,
               int M, int N, int K)
{
    extern __shared__ char smem[];
    float* bias_s = (float*)(smem + SMEM_BIAS);
    const uint32_t tiles_u32 = smem_u32(smem + SMEM_TILES);

    const int tid  = threadIdx.x;
    const int wid  = tid >> 5, lane = tid & 31;
    const int g    = lane >> 2, tg = lane & 3;
    const int wm   = wid & 1, wn = wid >> 1;          // 2 x 2 warp grid

    // grouped rasterization
    const int num_n = N / BN;
    const int tpg   = GROUP_M * num_n;
    const int grp   = blockIdx.x / tpg;
    const int rem   = blockIdx.x % tpg;
    const int m0 = (grp * GROUP_M + rem % GROUP_M) * BM;
    const int n0 = (rem / GROUP_M) * BN;

    bias_s[tid] = bias[n0 + tid];

    const int KT = K / BK;

    // stage loader: 4 A + 4 B 16B chunks per thread; consecutive lanes ->
    // consecutive 16B of one 64B row (full-sector coalescing).
    auto load_stage = [&](int s, int kt) {
        const uint32_t base = tiles_u32 + s * STAGE_BYTES;
        const int cg = tid & 3;
        #pragma unroll
        for (int j = 0; j < 4; j++) {
            const int row = (tid + j * 128) >> 2;
            cp16(base + row * 64 + cg * 16,
                 A + (size_t)(m0 + row) * K + kt * BK + cg * 8);
            cp16(base + 8192 + row * 64 + cg * 16,
                 Bt + (size_t)(n0 + row) * K + kt * BK + cg * 8);
        }
    };

    #pragma unroll
    for (int s = 0; s < STAGES - 1; s++) { load_stage(s, s); CP_COMMIT(); }

    float acc[4][8][4];
    #pragma unroll
    for (int im = 0; im < 4; im++)
        #pragma unroll
        for (int in = 0; in < 8; in++)
            #pragma unroll
            for (int q = 0; q < 4; q++) acc[im][in][q] = 0.f;

    int cs = 0;                       // compute stage (= kt mod STAGES)
    int ps = STAGES - 1;              // prefetch stage (= kt+STAGES-1 mod STAGES)
    for (int kt = 0; kt < KT; kt++) {
        CP_WAIT(STAGES - 2);
        __syncthreads();     // stage cs ready; orders prev reads before overwrite

        const int kn = kt + STAGES - 1;
        if (kn < KT) load_stage(ps, kn);
        CP_COMMIT();
        if (++ps == STAGES) ps = 0;

        const uint4* As4 = (const uint4*)(smem + SMEM_TILES + cs * STAGE_BYTES);
        const uint4* Bs4 = As4 + 512;
        if (++cs == STAGES) cs = 0;

        // one uint4 per row/col covers both k16 MMA steps (K-perm layout)
        uint4 a[4][2];
        #pragma unroll
        for (int im = 0; im < 4; im++)
            #pragma unroll
            for (int h = 0; h < 2; h++)
                a[im][h] = As4[(wm * 64 + im * 16 + h * 8 + g) * 4 + tg];

        #pragma unroll
        for (int half = 0; half < 2; half++) {
            uint4 b[4];
            #pragma unroll
            for (int i = 0; i < 4; i++)
                b[i] = Bs4[(wn * 64 + half * 32 + i * 8 + g) * 4 + tg];
            #pragma unroll
            for (int im = 0; im < 4; im++)
                #pragma unroll
                for (int i = 0; i < 4; i++) {
                    float* c = acc[im][half * 4 + i];
                    // k[0:16)
                    mma_bf16(c, a[im][0].x, a[im][1].x, a[im][0].y, a[im][1].y,
                             b[i].x, b[i].y);
                    // k[16:32)
                    mma_bf16(c, a[im][0].z, a[im][1].z, a[im][0].w, a[im][1].w,
                             b[i].z, b[i].w);
                }
        }
    }

    // -------- epilogue -----------------------------------------------------
    #pragma unroll
    for (int im = 0; im < 4; im++) {
        #pragma unroll
        for (int in = 0; in < 8; in++) {
            const int cl = wn * 64 + in * 8 + 2 * tg;
            #pragma unroll
            for (int h = 0; h < 2; h++) {
                const int row = m0 + wm * 64 + im * 16 + g + 8 * h;
                float v0 = acc[im][in][2 * h]     + bias_s[cl];
                float v1 = acc[im][in][2 * h + 1] + bias_s[cl + 1];
                if (ACT == 0) {
                    v0 = fmaxf(v0, 0.f);
                    v1 = fmaxf(v1, 0.f);
                    const int c0 = n0 + cl;                     // even
                    const int kk = c0 & 31;
                    const int pos = (c0 & ~31) + ((kk >> 1) & 3) * 8 + ((kk >> 3) << 1);
                    *(__nv_bfloat162*)((__nv_bfloat16*)Cv + (size_t)row * N + pos) =
                        __floats2bfloat162_rn(v0, v1);
                } else {
                    v0 = 1.f / (1.f + __expf(-v0));
                    v1 = 1.f / (1.f + __expf(-v1));
                    *(float2*)((float*)Cv + (size_t)row * N + n0 + cl) =
                        make_float2(v0, v1);
                }
            }
        }
    }
}

// ---------------------------------------------------------------------------
// Kernel A: capsule argmax mask + FC1 (effective K=16, fp32) + ReLU,
// bf16 K-permuted store.
// ---------------------------------------------------------------------------
__global__ void mask_fc1_kernel(const float* __restrict__ x,
                                const float* __restrict__ W1,
                                const float* __restrict__ b1)
{
    __shared__ float xs[D_IN];
    __shared__ float n2[10];
    __shared__ int   jm;

    const int b = blockIdx.x;
    const float* xr = x + (size_t)b * D_IN;

    for (int i = threadIdx.x; i < D_IN; i += blockDim.x) xs[i] = xr[i];
    __syncthreads();

    if (threadIdx.x < 10) {
        float s = 0.f;
        #pragma unroll
        for (int u = 0; u < 16; u++) { float v = xs[threadIdx.x * 16 + u]; s += v * v; }
        n2[threadIdx.x] = s;
    }
    __syncthreads();
    if (threadIdx.x == 0) {
        int best = 0; float bv = n2[0];
        #pragma unroll
        for (int j = 1; j < 10; j++) if (n2[j] > bv) { bv = n2[j]; best = j; }
        jm = best;
    }
    __syncthreads();

    const int base = jm * 16;
    for (int c = threadIdx.x; c < D_H1; c += blockDim.x) {
        float acc = b1[c];
        #pragma unroll
        for (int u = 0; u < 16; u++)
            acc += xs[base + u] * W1[(size_t)(base + u) * D_H1 + c];
        g_h1[(size_t)b * D_H1 + (c & ~31) + kperm32(c & 31)] =
            __float2bfloat16_rn(fmaxf(acc, 0.f));
    }
}

// ---------------------------------------------------------------------------
// Transpose + bf16 + K-perm:  W [K,N] fp32 -> Wt [N,K] bf16 (K-perm32)
// grid (N/32, K/32), block (32, 8)
// ---------------------------------------------------------------------------
__global__ void transpose_kernel(const float* __restrict__ W, __nv_bfloat16* __restrict__ Wt,
                                 int K, int N)
{
    __shared__ float t[32][33];
    const int k0 = blockIdx.y * 32, n0 = blockIdx.x * 32;
    #pragma unroll
    for (int j = 0; j < 4; j++) {
        int k = threadIdx.y + j * 8;
        t[k][threadIdx.x] = W[(size_t)(k0 + k) * N + n0 + threadIdx.x];
    }
    __syncthreads();
    #pragma unroll
    for (int j = 0; j < 4; j++) {
        int n = threadIdx.y + j * 8;
        int kk = k0 + threadIdx.x;
        Wt[(size_t)(n0 + n) * K + (kk & ~31) + kperm32(kk & 31)] =
            __float2bfloat16_rn(t[threadIdx.x][n]);
    }
}

// ---------------------------------------------------------------------------
extern "C" void kernel_launch(void* const* d_in, const int* in_sizes, int n_in,
                              void* d_out, int out_size)
{
    const float* x  = (const float*)d_in[0];
    const float* W1 = (const float*)d_in[2];
    const float* b1 = (const float*)d_in[3];
    const float* W2 = (const float*)d_in[4];
    const float* b2 = (const float*)d_in[5];
    const float* W3 = (const float*)d_in[6];
    const float* b3 = (const float*)d_in[7];
    float* out = (float*)d_out;

    __nv_bfloat16 *h1, *h2, *w2t, *w3t;
    cudaGetSymbolAddress((void**)&h1,  g_h1);
    cudaGetSymbolAddress((void**)&h2,  g_h2);
    cudaGetSymbolAddress((void**)&w2t, g_w2t);
    cudaGetSymbolAddress((void**)&w3t, g_w3t);

    cudaFuncSetAttribute(gemm_bf16<0>, cudaFuncAttributeMaxDynamicSharedMemorySize, SMEM_DYN);
    cudaFuncSetAttribute(gemm_bf16<1>, cudaFuncAttributeMaxDynamicSharedMemorySize, SMEM_DYN);

    transpose_kernel<<<dim3(D_H2 / 32, D_H1 / 32), dim3(32, 8)>>>(W2, w2t, D_H1, D_H2);
    transpose_kernel<<<dim3(D_OUT / 32, D_H2 / 32), dim3(32, 8)>>>(W3, w3t, D_H2, D_OUT);

    mask_fc1_kernel<<<BATCH, 128>>>(x, W1, b1);

    // h2 = relu(h1 @ W2 + b2), bf16 K-permuted
    gemm_bf16<0><<<(BATCH / BM) * (D_H2 / BN), 128, SMEM_DYN>>>(
        h1, w2t, b2, h2, BATCH, D_H2, D_H1);

    // out = sigmoid(h2 @ W3 + b3), fp32
    gemm_bf16<1><<<(BATCH / BM) * (D_OUT / BN), 128, SMEM_DYN>>>(
        h2, w3t, b3, out, BATCH, D_OUT, D_H2);
}

// round 9
// speedup vs baseline: 2.7863x; 1.1551x over previous
#include <cuda_runtime.h>
#include <cuda_bf16.h>
#include <cstdint>

#define BATCH   32768
#define D_IN    160
#define D_H1    512
#define D_H2    1024
#define D_OUT   3072

// ---------------- scratch (static device arrays; allocation-free) -----------
// GEMM operands in bf16, K-permuted per 32-element block:
// element k lives at pos = ((k>>1)&3)*8 + ((k>>3)<<1) + (k&1), so thread tg's
// 16B chunk holds k = {2tg,2tg+1, 8+2tg,8+2tg+1, 16+2tg,16+2tg+1, 24+2tg,24+2tg+1}.
__device__ __nv_bfloat16 g_h1[BATCH * D_H1];    // 32 MB
__device__ __nv_bfloat16 g_h2[BATCH * D_H2];    // 64 MB
__device__ __nv_bfloat16 g_w2t[D_H2 * D_H1];    //  1 MB  W2^T [1024,512]
__device__ __nv_bfloat16 g_w3t[D_OUT * D_H2];   //  6 MB  W3^T [3072,1024]

// ---------------- helpers ---------------------------------------------------
__device__ __forceinline__ uint32_t smem_u32(const void* p) {
    uint32_t a;
    asm("{ .reg .u64 t; cvta.to.shared.u64 t, %1; cvt.u32.u64 %0, t; }" : "=r"(a) : "l"(p));
    return a;
}
__device__ __forceinline__ int kperm32(int k) {           // k in [0,32)
    return ((k >> 1) & 3) * 8 + ((k >> 3) << 1) + (k & 1);
}
__device__ __forceinline__ void cp16(uint32_t dst, const void* src) {
    asm volatile("cp.async.cg.shared.global [%0], [%1], 16;" :: "r"(dst), "l"(src));
}
#define CP_COMMIT()  asm volatile("cp.async.commit_group;" ::: "memory")
#define CP_WAIT(n)   asm volatile("cp.async.wait_group %0;" :: "n"(n) : "memory")

__device__ __forceinline__ void mma_bf16(float* c,
                                         uint32_t a0, uint32_t a1, uint32_t a2, uint32_t a3,
                                         uint32_t b0, uint32_t b1) {
    asm volatile(
        "mma.sync.aligned.m16n8k16.row.col.f32.bf16.bf16.f32 "
        "{%0,%1,%2,%3}, {%4,%5,%6,%7}, {%8,%9}, {%0,%1,%2,%3};"
        : "+f"(c[0]), "+f"(c[1]), "+f"(c[2]), "+f"(c[3])
        : "r"(a0), "r"(a1), "r"(a2), "r"(a3), "r"(b0), "r"(b1));
}

// ---------------- GEMM config ----------------------------------------------
#define BM 128
#define BN 128
#define BK 32
#define STAGES 6
#define STAGE_BYTES (2 * BM * BK * 2)              // 16384 (A 8K + B 8K)
#define SMEM_BIAS   0
#define SMEM_TILES  1024
#define SMEM_DYN    (SMEM_TILES + STAGES * STAGE_BYTES)   // 99328 -> 2 CTAs/SM
#define GROUP_M 16

// ---------------------------------------------------------------------------
// Pipelined bf16 mma.sync GEMM:  C[M,N] = act(A[M,K] @ Bt[N,K]^T + bias)
// A [M,K], Bt [N,K] bf16, row-major, K-permuted per 32-block.
// 128 threads, 4 warps (2x2), warp tile 64x64, 6-stage cp.async pipeline,
// one barrier per K-tile, fp32 accumulate, 2 CTAs/SM.
// Register fragments software-pipelined across the barrier: frags for tile
// kt+1 are LDS'ed at the tail of iteration kt (data guaranteed by deeper
// CP_WAIT; slot overwritten only 2 barriers later), so every iteration opens
// with immediately-issueable HMMAs.
// ACT: 0 = relu, bf16 K-permuted stores;  1 = sigmoid, fp32 stores
// ---------------------------------------------------------------------------
template <int ACT>
__global__ __launch_bounds__(128, 2)
void gemm_bf16(const __nv_bfloat16* __restrict__ A, const __nv_bfloat16* __restrict__ Bt,
               const float* __restrict__ bias, void* __restrict__ Cv,
               int M, int N, int K)
{
    extern __shared__ char smem[];
    float* bias_s = (float*)(smem + SMEM_BIAS);
    const uint32_t tiles_u32 = smem_u32(smem + SMEM_TILES);

    const int tid  = threadIdx.x;
    const int wid  = tid >> 5, lane = tid & 31;
    const int g    = lane >> 2, tg = lane & 3;
    const int wm   = wid & 1, wn = wid >> 1;          // 2 x 2 warp grid

    // grouped rasterization
    const int num_n = N / BN;
    const int tpg   = GROUP_M * num_n;
    const int grp   = blockIdx.x / tpg;
    const int rem   = blockIdx.x % tpg;
    const int m0 = (grp * GROUP_M + rem % GROUP_M) * BM;
    const int n0 = (rem / GROUP_M) * BN;

    bias_s[tid] = bias[n0 + tid];

    const int KT = K / BK;

    // stage loader: 4 A + 4 B 16B chunks per thread; consecutive lanes ->
    // consecutive 16B of one 64B row (full-sector coalescing).
    auto load_stage = [&](int s, int kt) {
        const uint32_t base = tiles_u32 + s * STAGE_BYTES;
        const int cg = tid & 3;
        #pragma unroll
        for (int j = 0; j < 4; j++) {
            const int row = (tid + j * 128) >> 2;
            cp16(base + row * 64 + cg * 16,
                 A + (size_t)(m0 + row) * K + kt * BK + cg * 8);
            cp16(base + 8192 + row * 64 + cg * 16,
                 Bt + (size_t)(n0 + row) * K + kt * BK + cg * 8);
        }
    };

    // fragment loader: all frags for one tile from stage s (16 LDS.128)
    uint4 a[4][2], b[2][4];
    auto frag_load = [&](int s) {
        const uint4* As4 = (const uint4*)(smem + SMEM_TILES + s * STAGE_BYTES);
        const uint4* Bs4 = As4 + 512;
        #pragma unroll
        for (int im = 0; im < 4; im++)
            #pragma unroll
            for (int h = 0; h < 2; h++)
                a[im][h] = As4[(wm * 64 + im * 16 + h * 8 + g) * 4 + tg];
        #pragma unroll
        for (int half = 0; half < 2; half++)
            #pragma unroll
            for (int i = 0; i < 4; i++)
                b[half][i] = Bs4[(wn * 64 + half * 32 + i * 8 + g) * 4 + tg];
    };

    // prologue: fill STAGES-1 stages, then pre-load frags for tile 0
    #pragma unroll
    for (int s = 0; s < STAGES - 1; s++) { load_stage(s, s); CP_COMMIT(); }
    CP_WAIT(STAGES - 2);                  // tile 0 arrived
    __syncthreads();
    frag_load(0);

    float acc[4][8][4];
    #pragma unroll
    for (int im = 0; im < 4; im++)
        #pragma unroll
        for (int in = 0; in < 8; in++)
            #pragma unroll
            for (int q = 0; q < 4; q++) acc[im][in][q] = 0.f;

    int cs = 0;                       // stage holding tile kt's data
    int ps = STAGES - 1;              // stage to prefetch into
    for (int kt = 0; kt < KT; kt++) {
        // barrier: all warps finished reading the slot that the prefetch
        // below overwrites (slot (kt-1)%S, read during iteration kt-1)
        __syncthreads();

        const int kn = kt + STAGES - 1;
        if (kn < KT) load_stage(ps, kn);
        CP_COMMIT();
        if (++ps == STAGES) ps = 0;

        // compute: 64 HMMA on pre-loaded frags — issueable immediately
        #pragma unroll
        for (int half = 0; half < 2; half++)
            #pragma unroll
            for (int im = 0; im < 4; im++)
                #pragma unroll
                for (int i = 0; i < 4; i++) {
                    float* c = acc[im][half * 4 + i];
                    mma_bf16(c, a[im][0].x, a[im][1].x, a[im][0].y, a[im][1].y,
                             b[half][i].x, b[half][i].y);
                    mma_bf16(c, a[im][0].z, a[im][1].z, a[im][0].w, a[im][1].w,
                             b[half][i].z, b[half][i].w);
                }

        if (++cs == STAGES) cs = 0;
        if (kt + 1 < KT) {
            CP_WAIT(STAGES - 3);          // guarantees tile kt+1 resident
            frag_load(cs);                // tail LDS overlap barrier + next MMAs
        }
    }

    // -------- epilogue -----------------------------------------------------
    #pragma unroll
    for (int im = 0; im < 4; im++) {
        #pragma unroll
        for (int in = 0; in < 8; in++) {
            const int cl = (in >> 2) * 32 * 0 + wn * 64 + (in & 7) * 8 + 2 * tg;
            #pragma unroll
            for (int h = 0; h < 2; h++) {
                const int row = m0 + wm * 64 + im * 16 + g + 8 * h;
                float v0 = acc[im][in][2 * h]     + bias_s[cl];
                float v1 = acc[im][in][2 * h + 1] + bias_s[cl + 1];
                if (ACT == 0) {
                    v0 = fmaxf(v0, 0.f);
                    v1 = fmaxf(v1, 0.f);
                    const int c0 = n0 + cl;                     // even
                    const int kk = c0 & 31;
                    const int pos = (c0 & ~31) + ((kk >> 1) & 3) * 8 + ((kk >> 3) << 1);
                    *(__nv_bfloat162*)((__nv_bfloat16*)Cv + (size_t)row * N + pos) =
                        __floats2bfloat162_rn(v0, v1);
                } else {
                    v0 = 1.f / (1.f + __expf(-v0));
                    v1 = 1.f / (1.f + __expf(-v1));
                    *(float2*)((float*)Cv + (size_t)row * N + n0 + cl) =
                        make_float2(v0, v1);
                }
            }
        }
    }
}

// ---------------------------------------------------------------------------
// Kernel A: capsule argmax mask + FC1 (effective K=16, fp32) + ReLU,
// bf16 K-permuted store.
// ---------------------------------------------------------------------------
__global__ void mask_fc1_kernel(const float* __restrict__ x,
                                const float* __restrict__ W1,
                                const float* __restrict__ b1)
{
    __shared__ float xs[D_IN];
    __shared__ float n2[10];
    __shared__ int   jm;

    const int b = blockIdx.x;
    const float* xr = x + (size_t)b * D_IN;

    for (int i = threadIdx.x; i < D_IN; i += blockDim.x) xs[i] = xr[i];
    __syncthreads();

    if (threadIdx.x < 10) {
        float s = 0.f;
        #pragma unroll
        for (int u = 0; u < 16; u++) { float v = xs[threadIdx.x * 16 + u]; s += v * v; }
        n2[threadIdx.x] = s;
    }
    __syncthreads();
    if (threadIdx.x == 0) {
        int best = 0; float bv = n2[0];
        #pragma unroll
        for (int j = 1; j < 10; j++) if (n2[j] > bv) { bv = n2[j]; best = j; }
        jm = best;
    }
    __syncthreads();

    const int base = jm * 16;
    for (int c = threadIdx.x; c < D_H1; c += blockDim.x) {
        float acc = b1[c];
        #pragma unroll
        for (int u = 0; u < 16; u++)
            acc += xs[base + u] * W1[(size_t)(base + u) * D_H1 + c];
        g_h1[(size_t)b * D_H1 + (c & ~31) + kperm32(c & 31)] =
            __float2bfloat16_rn(fmaxf(acc, 0.f));
    }
}

// ---------------------------------------------------------------------------
// Transpose + bf16 + K-perm:  W [K,N] fp32 -> Wt [N,K] bf16 (K-perm32)
// grid (N/32, K/32), block (32, 8)
// ---------------------------------------------------------------------------
__global__ void transpose_kernel(const float* __restrict__ W, __nv_bfloat16* __restrict__ Wt,
                                 int K, int N)
{
    __shared__ float t[32][33];
    const int k0 = blockIdx.y * 32, n0 = blockIdx.x * 32;
    #pragma unroll
    for (int j = 0; j < 4; j++) {
        int k = threadIdx.y + j * 8;
        t[k][threadIdx.x] = W[(size_t)(k0 + k) * N + n0 + threadIdx.x];
    }
    __syncthreads();
    #pragma unroll
    for (int j = 0; j < 4; j++) {
        int n = threadIdx.y + j * 8;
        int kk = k0 + threadIdx.x;
        Wt[(size_t)(n0 + n) * K + (kk & ~31) + kperm32(kk & 31)] =
            __float2bfloat16_rn(t[threadIdx.x][n]);
    }
}

// ---------------------------------------------------------------------------
extern "C" void kernel_launch(void* const* d_in, const int* in_sizes, int n_in,
                              void* d_out, int out_size)
{
    const float* x  = (const float*)d_in[0];
    const float* W1 = (const float*)d_in[2];
    const float* b1 = (const float*)d_in[3];
    const float* W2 = (const float*)d_in[4];
    const float* b2 = (const float*)d_in[5];
    const float* W3 = (const float*)d_in[6];
    const float* b3 = (const float*)d_in[7];
    float* out = (float*)d_out;

    __nv_bfloat16 *h1, *h2, *w2t, *w3t;
    cudaGetSymbolAddress((void**)&h1,  g_h1);
    cudaGetSymbolAddress((void**)&h2,  g_h2);
    cudaGetSymbolAddress((void**)&w2t, g_w2t);
    cudaGetSymbolAddress((void**)&w3t, g_w3t);

    cudaFuncSetAttribute(gemm_bf16<0>, cudaFuncAttributeMaxDynamicSharedMemorySize, SMEM_DYN);
    cudaFuncSetAttribute(gemm_bf16<1>, cudaFuncAttributeMaxDynamicSharedMemorySize, SMEM_DYN);

    transpose_kernel<<<dim3(D_H2 / 32, D_H1 / 32), dim3(32, 8)>>>(W2, w2t, D_H1, D_H2);
    transpose_kernel<<<dim3(D_OUT / 32, D_H2 / 32), dim3(32, 8)>>>(W3, w3t, D_H2, D_OUT);

    mask_fc1_kernel<<<BATCH, 128>>>(x, W1, b1);

    // h2 = relu(h1 @ W2 + b2), bf16 K-permuted
    gemm_bf16<0><<<(BATCH / BM) * (D_H2 / BN), 128, SMEM_DYN>>>(
        h1, w2t, b2, h2, BATCH, D_H2, D_H1);

    // out = sigmoid(h2 @ W3 + b3), fp32
    gemm_bf16<1><<<(BATCH / BM) * (D_OUT / BN), 128, SMEM_DYN>>>(
        h2, w3t, b3, out, BATCH, D_OUT, D_H2);
}

// round 10
// speedup vs baseline: 2.8316x; 1.0163x over previous
#include <cuda_runtime.h>
#include <cuda_bf16.h>
#include <cstdint>

#define BATCH   32768
#define D_IN    160
#define D_H1    512
#define D_H2    1024
#define D_OUT   3072

// ---------------- scratch (static device arrays; allocation-free) -----------
// GEMM operands in bf16, K-permuted per 32-element block:
// element k lives at pos = ((k>>1)&3)*8 + ((k>>3)<<1) + (k&1).
__device__ __nv_bfloat16 g_h1[BATCH * D_H1];    // 32 MB
__device__ __nv_bfloat16 g_h2[BATCH * D_H2];    // 64 MB
__device__ __nv_bfloat16 g_w1b[D_IN * D_H1];    // 160KB  W1 bf16 (same layout)
__device__ __nv_bfloat16 g_w2t[D_H2 * D_H1];    //  1 MB  W2^T [1024,512]
__device__ __nv_bfloat16 g_w3t[D_OUT * D_H2];   //  6 MB  W3^T [3072,1024]

// ---------------- helpers ---------------------------------------------------
__device__ __forceinline__ uint32_t smem_u32(const void* p) {
    uint32_t a;
    asm("{ .reg .u64 t; cvta.to.shared.u64 t, %1; cvt.u32.u64 %0, t; }" : "=r"(a) : "l"(p));
    return a;
}
__device__ __forceinline__ int kperm32(int k) {           // k in [0,32)
    return ((k >> 1) & 3) * 8 + ((k >> 3) << 1) + (k & 1);
}
__device__ __forceinline__ void cp16(uint32_t dst, const void* src) {
    asm volatile("cp.async.cg.shared.global [%0], [%1], 16;" :: "r"(dst), "l"(src));
}
#define CP_COMMIT()  asm volatile("cp.async.commit_group;" ::: "memory")
#define CP_WAIT(n)   asm volatile("cp.async.wait_group %0;" :: "n"(n) : "memory")

__device__ __forceinline__ void mma_bf16(float* c,
                                         uint32_t a0, uint32_t a1, uint32_t a2, uint32_t a3,
                                         uint32_t b0, uint32_t b1) {
    asm volatile(
        "mma.sync.aligned.m16n8k16.row.col.f32.bf16.bf16.f32 "
        "{%0,%1,%2,%3}, {%4,%5,%6,%7}, {%8,%9}, {%0,%1,%2,%3};"
        : "+f"(c[0]), "+f"(c[1]), "+f"(c[2]), "+f"(c[3])
        : "r"(a0), "r"(a1), "r"(a2), "r"(a3), "r"(b0), "r"(b1));
}

// ---------------- GEMM config ----------------------------------------------
#define BM 128
#define BN 128
#define BK 32
#define STAGES 6
#define PFD 4                                      // prefetch distance (tiles)
#define STAGE_BYTES (2 * BM * BK * 2)              // 16384 (A 8K + B 8K)
#define SMEM_BIAS   0
#define SMEM_TILES  1024
#define SMEM_DYN    (SMEM_TILES + STAGES * STAGE_BYTES)   // 99328 -> 2 CTAs/SM
#define GROUP_M 16

// ---------------------------------------------------------------------------
// Pipelined bf16 mma.sync GEMM:  C[M,N] = act(A[M,K] @ Bt[N,K]^T + bias)
// 128 threads, 4 warps (2x2), warp tile 64x64, 6-stage cp.async pipeline,
// prefetch distance 4, __syncthreads only every SECOND K-tile (slot written
// at iter kt was last read at iter kt-2; a barrier in {kt-1, kt} suffices),
// register fragments preloaded across the barrier, fp32 accumulate, 2 CTAs/SM.
// ACT: 0 = relu, bf16 K-permuted stores;  1 = sigmoid, fp32 stores
// ---------------------------------------------------------------------------
template <int ACT>
__global__ __launch_bounds__(128, 2)
void gemm_bf16(const __nv_bfloat16* __restrict__ A, const __nv_bfloat16* __restrict__ Bt,
               const float* __restrict__ bias, void* __restrict__ Cv,
               int M, int N, int K)
{
    extern __shared__ char smem[];
    float* bias_s = (float*)(smem + SMEM_BIAS);
    const uint32_t tiles_u32 = smem_u32(smem + SMEM_TILES);

    const int tid  = threadIdx.x;
    const int wid  = tid >> 5, lane = tid & 31;
    const int g    = lane >> 2, tg = lane & 3;
    const int wm   = wid & 1, wn = wid >> 1;          // 2 x 2 warp grid

    // grouped rasterization
    const int num_n = N / BN;
    const int tpg   = GROUP_M * num_n;
    const int grp   = blockIdx.x / tpg;
    const int rem   = blockIdx.x % tpg;
    const int m0 = (grp * GROUP_M + rem % GROUP_M) * BM;
    const int n0 = (rem / GROUP_M) * BN;

    bias_s[tid] = bias[n0 + tid];

    const int KT = K / BK;

    // stage loader: 4 A + 4 B 16B chunks per thread; consecutive lanes ->
    // consecutive 16B of one 64B row (full-sector coalescing).
    auto load_stage = [&](int s, int kt) {
        const uint32_t base = tiles_u32 + s * STAGE_BYTES;
        const int cg = tid & 3;
        #pragma unroll
        for (int j = 0; j < 4; j++) {
            const int row = (tid + j * 128) >> 2;
            cp16(base + row * 64 + cg * 16,
                 A + (size_t)(m0 + row) * K + kt * BK + cg * 8);
            cp16(base + 8192 + row * 64 + cg * 16,
                 Bt + (size_t)(n0 + row) * K + kt * BK + cg * 8);
        }
    };

    // fragment loader: all frags for one tile from stage s (16 LDS.128)
    uint4 a[4][2], b[2][4];
    auto frag_load = [&](int s) {
        const uint4* As4 = (const uint4*)(smem + SMEM_TILES + s * STAGE_BYTES);
        const uint4* Bs4 = As4 + 512;
        #pragma unroll
        for (int im = 0; im < 4; im++)
            #pragma unroll
            for (int h = 0; h < 2; h++)
                a[im][h] = As4[(wm * 64 + im * 16 + h * 8 + g) * 4 + tg];
        #pragma unroll
        for (int half = 0; half < 2; half++)
            #pragma unroll
            for (int i = 0; i < 4; i++)
                b[half][i] = Bs4[(wn * 64 + half * 32 + i * 8 + g) * 4 + tg];
    };

    // prologue: fill PFD stages, then pre-load frags for tile 0
    #pragma unroll
    for (int s = 0; s < PFD; s++) { load_stage(s, s); CP_COMMIT(); }
    CP_WAIT(PFD - 1);                 // tile 0 arrived
    __syncthreads();
    frag_load(0);

    float acc[4][8][4];
    #pragma unroll
    for (int im = 0; im < 4; im++)
        #pragma unroll
        for (int in = 0; in < 8; in++)
            #pragma unroll
            for (int q = 0; q < 4; q++) acc[im][in][q] = 0.f;

    int cs = 0;                       // stage holding tile kt's data
    int ps = PFD;                     // stage to prefetch into
    for (int kt = 0; kt < KT; kt++) {
        if (!(kt & 1)) __syncthreads();   // protects slot reuse (2-iter window)

        const int kn = kt + PFD;
        if (kn < KT) load_stage(ps, kn);
        CP_COMMIT();
        if (++ps == STAGES) ps = 0;

        // compute: 64 HMMA on pre-loaded frags — issueable immediately
        #pragma unroll
        for (int half = 0; half < 2; half++)
            #pragma unroll
            for (int im = 0; im < 4; im++)
                #pragma unroll
                for (int i = 0; i < 4; i++) {
                    float* c = acc[im][half * 4 + i];
                    mma_bf16(c, a[im][0].x, a[im][1].x, a[im][0].y, a[im][1].y,
                             b[half][i].x, b[half][i].y);
                    mma_bf16(c, a[im][0].z, a[im][1].z, a[im][0].w, a[im][1].w,
                             b[half][i].z, b[half][i].w);
                }

        if (++cs == STAGES) cs = 0;
        if (kt + 1 < KT) {
            CP_WAIT(3);                   // tile kt+1 resident (4 groups max out)
            frag_load(cs);                // tail LDS overlap next iter's MMAs
        }
    }

    // -------- epilogue -----------------------------------------------------
    #pragma unroll
    for (int im = 0; im < 4; im++) {
        #pragma unroll
        for (int in = 0; in < 8; in++) {
            const int cl = wn * 64 + in * 8 + 2 * tg;
            #pragma unroll
            for (int h = 0; h < 2; h++) {
                const int row = m0 + wm * 64 + im * 16 + g + 8 * h;
                float v0 = acc[im][in][2 * h]     + bias_s[cl];
                float v1 = acc[im][in][2 * h + 1] + bias_s[cl + 1];
                if (ACT == 0) {
                    v0 = fmaxf(v0, 0.f);
                    v1 = fmaxf(v1, 0.f);
                    const int c0 = n0 + cl;                     // even
                    const int kk = c0 & 31;
                    const int pos = (c0 & ~31) + ((kk >> 1) & 3) * 8 + ((kk >> 3) << 1);
                    *(__nv_bfloat162*)((__nv_bfloat16*)Cv + (size_t)row * N + pos) =
                        __floats2bfloat162_rn(v0, v1);
                } else {
                    v0 = 1.f / (1.f + __expf(-v0));
                    v1 = 1.f / (1.f + __expf(-v1));
                    *(float2*)((float*)Cv + (size_t)row * N + n0 + cl) =
                        make_float2(v0, v1);
                }
            }
        }
    }
}

// ---------------------------------------------------------------------------
// W1 fp32 -> bf16 copy (same layout), 1D
// ---------------------------------------------------------------------------
__global__ void pack_w1_kernel(const float* __restrict__ W1)
{
    int i = blockIdx.x * 256 + threadIdx.x;
    if (i < D_IN * D_H1) g_w1b[i] = __float2bfloat16_rn(W1[i]);
}

// ---------------------------------------------------------------------------
// Kernel A: capsule argmax mask + FC1 (effective K=16) + ReLU.
// 128 threads; each thread handles 4 consecutive cols via 64-bit bf16x4 loads
// of the bf16 W1. bf16 K-permuted store (pairs (4t,4t+1),(4t+2,4t+3) are
// contiguous under kperm32).
// ---------------------------------------------------------------------------
__global__ void mask_fc1_kernel(const float* __restrict__ x,
                                const float* __restrict__ b1)
{
    __shared__ float xs[D_IN];
    __shared__ float n2[10];
    __shared__ int   jm;

    const int b = blockIdx.x;
    const float* xr = x + (size_t)b * D_IN;

    for (int i = threadIdx.x; i < D_IN; i += blockDim.x) xs[i] = xr[i];
    __syncthreads();

    if (threadIdx.x < 10) {
        float s = 0.f;
        #pragma unroll
        for (int u = 0; u < 16; u++) { float v = xs[threadIdx.x * 16 + u]; s += v * v; }
        n2[threadIdx.x] = s;
    }
    __syncthreads();
    if (threadIdx.x == 0) {
        int best = 0; float bv = n2[0];
        #pragma unroll
        for (int j = 1; j < 10; j++) if (n2[j] > bv) { bv = n2[j]; best = j; }
        jm = best;
    }
    __syncthreads();

    const int base = jm * 16;
    const int c0 = threadIdx.x * 4;                    // 4 cols per thread
    float s0, s1, s2, s3;
    {
        float bb0 = b1[c0], bb1 = b1[c0 + 1], bb2 = b1[c0 + 2], bb3 = b1[c0 + 3];
        s0 = bb0; s1 = bb1; s2 = bb2; s3 = bb3;
    }
    #pragma unroll
    for (int u = 0; u < 16; u++) {
        const __nv_bfloat162* w2p = (const __nv_bfloat162*)(g_w1b + (size_t)(base + u) * D_H1 + c0);
        __nv_bfloat162 wl = w2p[0], wh = w2p[1];
        const float xv = xs[base + u];
        s0 = fmaf(xv, __bfloat162float(wl.x), s0);
        s1 = fmaf(xv, __bfloat162float(wl.y), s1);
        s2 = fmaf(xv, __bfloat162float(wh.x), s2);
        s3 = fmaf(xv, __bfloat162float(wh.y), s3);
    }
    s0 = fmaxf(s0, 0.f); s1 = fmaxf(s1, 0.f);
    s2 = fmaxf(s2, 0.f); s3 = fmaxf(s3, 0.f);

    // K-perm store: pairs (c0,c0+1) and (c0+2,c0+3) are contiguous bf162
    __nv_bfloat16* out = g_h1 + (size_t)b * D_H1;
    const int k0 = c0 & 31;
    *(__nv_bfloat162*)(out + (c0 & ~31) + kperm32(k0))     = __floats2bfloat162_rn(s0, s1);
    *(__nv_bfloat162*)(out + (c0 & ~31) + kperm32(k0 + 2)) = __floats2bfloat162_rn(s2, s3);
}

// ---------------------------------------------------------------------------
// Transpose + bf16 + K-perm:  W [K,N] fp32 -> Wt [N,K] bf16 (K-perm32)
// grid (N/32, K/32), block (32, 8)
// ---------------------------------------------------------------------------
__global__ void transpose_kernel(const float* __restrict__ W, __nv_bfloat16* __restrict__ Wt,
                                 int K, int N)
{
    __shared__ float t[32][33];
    const int k0 = blockIdx.y * 32, n0 = blockIdx.x * 32;
    #pragma unroll
    for (int j = 0; j < 4; j++) {
        int k = threadIdx.y + j * 8;
        t[k][threadIdx.x] = W[(size_t)(k0 + k) * N + n0 + threadIdx.x];
    }
    __syncthreads();
    #pragma unroll
    for (int j = 0; j < 4; j++) {
        int n = threadIdx.y + j * 8;
        int kk = k0 + threadIdx.x;
        Wt[(size_t)(n0 + n) * K + (kk & ~31) + kperm32(kk & 31)] =
            __float2bfloat16_rn(t[threadIdx.x][n]);
    }
}

// ---------------------------------------------------------------------------
extern "C" void kernel_launch(void* const* d_in, const int* in_sizes, int n_in,
                              void* d_out, int out_size)
{
    const float* x  = (const float*)d_in[0];
    const float* W1 = (const float*)d_in[2];
    const float* b1 = (const float*)d_in[3];
    const float* W2 = (const float*)d_in[4];
    const float* b2 = (const float*)d_in[5];
    const float* W3 = (const float*)d_in[6];
    const float* b3 = (const float*)d_in[7];
    float* out = (float*)d_out;

    __nv_bfloat16 *h1, *h2, *w2t, *w3t;
    cudaGetSymbolAddress((void**)&h1,  g_h1);
    cudaGetSymbolAddress((void**)&h2,  g_h2);
    cudaGetSymbolAddress((void**)&w2t, g_w2t);
    cudaGetSymbolAddress((void**)&w3t, g_w3t);

    cudaFuncSetAttribute(gemm_bf16<0>, cudaFuncAttributeMaxDynamicSharedMemorySize, SMEM_DYN);
    cudaFuncSetAttribute(gemm_bf16<1>, cudaFuncAttributeMaxDynamicSharedMemorySize, SMEM_DYN);

    pack_w1_kernel<<<(D_IN * D_H1 + 255) / 256, 256>>>(W1);
    transpose_kernel<<<dim3(D_H2 / 32, D_H1 / 32), dim3(32, 8)>>>(W2, w2t, D_H1, D_H2);
    transpose_kernel<<<dim3(D_OUT / 32, D_H2 / 32), dim3(32, 8)>>>(W3, w3t, D_H2, D_OUT);

    mask_fc1_kernel<<<BATCH, 128>>>(x, b1);

    // h2 = relu(h1 @ W2 + b2), bf16 K-permuted
    gemm_bf16<0><<<(BATCH / BM) * (D_H2 / BN), 128, SMEM_DYN>>>(
        h1, w2t, b2, h2, BATCH, D_H2, D_H1);

    // out = sigmoid(h2 @ W3 + b3), fp32
    gemm_bf16<1><<<(BATCH / BM) * (D_OUT / BN), 128, SMEM_DYN>>>(
        h2, w3t, b3, out, BATCH, D_OUT, D_H2);
}